// round 9
// baseline (speedup 1.0000x reference)
#include <cuda_runtime.h>
#include <math.h>

#define T_ 256
#define B_ 32
#define E_ 256
#define H_ 256
#define K_ 48
#define M_ (T_*B_)      /* 8192 rows (t*B+b) */
#define G4_ 1024        /* 4*H */

typedef unsigned long long ull;

// ---------------- f32x2 packed helpers (FFMA2 path, sm_100+) ----------------
__device__ __forceinline__ ull ffma2(ull a, ull b, ull c) {
    ull d; asm("fma.rn.f32x2 %0, %1, %2, %3;" : "=l"(d) : "l"(a), "l"(b), "l"(c)); return d;
}
__device__ __forceinline__ ull add2(ull a, ull b) {
    ull d; asm("add.rn.f32x2 %0, %1, %2;" : "=l"(d) : "l"(a), "l"(b)); return d;
}
__device__ __forceinline__ ull pk2(float lo, float hi) {
    ull r; asm("mov.b64 %0, {%1, %2};" : "=l"(r) : "f"(lo), "f"(hi)); return r;
}
__device__ __forceinline__ void upk2(ull v, float& lo, float& hi) {
    asm("mov.b64 {%0, %1}, %2;" : "=f"(lo), "=f"(hi) : "l"(v));
}

// ---------------- scratch (device globals; no allocs allowed) ----------------
__device__ float g_emb [M_*E_];           // embedded input, (t*B+b, 256)
__device__ float g_xcat[M_*512];          // concat hf|hb,  (t*B+b, 512)
__device__ float g_pref[(size_t)M_*G4_];  // pre-gates fwd
__device__ float g_preb[(size_t)M_*G4_];  // pre-gates bwd
__device__ float g_emit[M_*K_];           // emit, (t*B+b, 48)
__device__ float g_h   [2*4*H_*B_];       // [layer][dirF buf0,buf1 | dirB buf0,buf1]
__device__ int   g_bar [2*2*T_];          // [layer][dir][step] counters
__device__ float g_part[B_];

// ---------------- init: zero h state + barriers each launch ----------------
__global__ void init_kernel() {
    int tid = blockIdx.x * blockDim.x + threadIdx.x;
    int n = blockDim.x * gridDim.x;
    for (int i = tid; i < 2*4*H_*B_; i += n) g_h[i] = 0.f;
    for (int i = tid; i < 2*2*T_; i += n) g_bar[i] = 0;
}

// ---------------- embedding gather + mask output ----------------
__global__ void embed_kernel(const int* __restrict__ sentence,
                             const float* __restrict__ embed,
                             float* __restrict__ out_mask) {
    int m = blockIdx.x;             // m = t*B + b
    int t = m >> 5, b = m & 31;
    int tok = sentence[b * T_ + t];
    const float4* src = (const float4*)(embed + (size_t)tok * E_);
    float4* dst = (float4*)(g_emb + (size_t)m * E_);
    dst[threadIdx.x] = src[threadIdx.x];        // 64 threads * float4 = 256
    if (threadIdx.x == 0) out_mask[b * T_ + t] = (tok != 0) ? 1.f : 0.f;
}

// ---------------- SGEMM (FFMA2): C[M,1024] = A[M,Kd] @ W[1024,Kd]^T + bias ---
// grid(16, 64, 2), block 256. BM=128, BN=64, BK=8, thread tile 8x4.
__global__ void gemm_pre(const float* __restrict__ A,
                         const float* __restrict__ Wf, const float* __restrict__ Wb,
                         const float* __restrict__ biasf, const float* __restrict__ biasb,
                         float* __restrict__ Cf, float* __restrict__ Cb, int Kd) {
    __shared__ float As[8][128];
    __shared__ float Bs[8][64];
    const float* W    = blockIdx.z ? Wb : Wf;
    const float* bias = blockIdx.z ? biasb : biasf;
    float*       C    = blockIdx.z ? Cb : Cf;

    int tid = threadIdx.x;
    int row0 = blockIdx.y * 128;
    int col0 = blockIdx.x * 64;
    int tr = tid >> 4, tc = tid & 15;      // 16x16 thread grid
    int ar = tid >> 1, ak = (tid & 1) * 4; // A load: 128 rows x 8k
    int wc = tid >> 2, wk = (tid & 3) * 2; // W load: 64 rows x 8k
    ull acc2[4][4];                        // [row-pair][col]
#pragma unroll
    for (int p = 0; p < 4; p++)
#pragma unroll
        for (int j = 0; j < 4; j++) acc2[p][j] = 0ull;

    for (int k0 = 0; k0 < Kd; k0 += 8) {
        float4 av = *(const float4*)(A + (size_t)(row0 + ar) * Kd + k0 + ak);
        float2 wv = *(const float2*)(W + (size_t)(col0 + wc) * Kd + k0 + wk);
        As[ak+0][ar] = av.x; As[ak+1][ar] = av.y; As[ak+2][ar] = av.z; As[ak+3][ar] = av.w;
        Bs[wk+0][wc] = wv.x; Bs[wk+1][wc] = wv.y;
        __syncthreads();
#pragma unroll
        for (int k = 0; k < 8; ++k) {
            ulonglong2 a01 = *(const ulonglong2*)&As[k][tr*8];     // row pairs (0,1),(2,3)
            ulonglong2 a23 = *(const ulonglong2*)&As[k][tr*8+4];   // (4,5),(6,7)
            float4 b4 = *(const float4*)&Bs[k][tc*4];
            ull bd0 = pk2(b4.x, b4.x), bd1 = pk2(b4.y, b4.y);
            ull bd2 = pk2(b4.z, b4.z), bd3 = pk2(b4.w, b4.w);
            acc2[0][0]=ffma2(a01.x,bd0,acc2[0][0]); acc2[0][1]=ffma2(a01.x,bd1,acc2[0][1]);
            acc2[0][2]=ffma2(a01.x,bd2,acc2[0][2]); acc2[0][3]=ffma2(a01.x,bd3,acc2[0][3]);
            acc2[1][0]=ffma2(a01.y,bd0,acc2[1][0]); acc2[1][1]=ffma2(a01.y,bd1,acc2[1][1]);
            acc2[1][2]=ffma2(a01.y,bd2,acc2[1][2]); acc2[1][3]=ffma2(a01.y,bd3,acc2[1][3]);
            acc2[2][0]=ffma2(a23.x,bd0,acc2[2][0]); acc2[2][1]=ffma2(a23.x,bd1,acc2[2][1]);
            acc2[2][2]=ffma2(a23.x,bd2,acc2[2][2]); acc2[2][3]=ffma2(a23.x,bd3,acc2[2][3]);
            acc2[3][0]=ffma2(a23.y,bd0,acc2[3][0]); acc2[3][1]=ffma2(a23.y,bd1,acc2[3][1]);
            acc2[3][2]=ffma2(a23.y,bd2,acc2[3][2]); acc2[3][3]=ffma2(a23.y,bd3,acc2[3][3]);
        }
        __syncthreads();
    }
#pragma unroll
    for (int p = 0; p < 4; p++) {
        int r0 = row0 + tr * 8 + 2 * p;
#pragma unroll
        for (int j = 0; j < 4; j++) {
            int c = col0 + tc * 4 + j;
            float lo, hi; upk2(acc2[p][j], lo, hi);
            float bv = bias[c];
            C[(size_t)r0 * G4_ + c]       = lo + bv;
            C[(size_t)(r0+1) * G4_ + c]   = hi + bv;
        }
    }
}

// ---------------- persistent BiLSTM layer: BOTH directions per block --------
// grid 64, block 256, dyn smem 115712B. Block owns 4 units x 32 batches x 2 dirs.
// Per step: F-phase then B-phase. Each dir's arrive gets a full opposite-phase
// (~2K cyc) to propagate before it is polled -> first-poll hit. All 8 warps run
// every phase (split-K GEMM as in R5). Central 64-arrive counter per dir.
__global__ void __launch_bounds__(256, 1)
lstm_layer(const float* __restrict__ pre_f, const float* __restrict__ pre_b,
           const float* __restrict__ Whh_f, const float* __restrict__ Whh_b,
           const int* __restrict__ lengths, float* __restrict__ xcat,
           int* __restrict__ bar, float* __restrict__ hbase) {
    extern __shared__ float sm[];
    float* w_f  = sm;                    // [256][16]
    float* w_b  = sm + 4096;
    float* h_f  = sm + 8192;             // [256][32]
    float* h_b  = sm + 16384;
    ull*  red_u = (ull*)(sm + 24576);    // [8][256] ull (shared by phases)
    float* c_f  = sm + 28672;            // [128]
    float* c_b  = sm + 28800;

    int tid = threadIdx.x;
    int blk = blockIdx.x;                // 0..63
    int u_base = blk * 4;

    // weight slices for both dirs: rows r = gate*4+ui
    for (int idx = tid; idx < 16 * 256; idx += 256) {
        int r = idx >> 8, k = idx & 255;
        int gate = r >> 2, ui = r & 3;
        size_t row = (size_t)(gate * 256 + u_base + ui) * 256 + k;
        w_f[k * 16 + r] = Whh_f[row];
        w_b[k * 16 + r] = Whh_b[row];
    }

    int warp = tid >> 5, lane = tid & 31;
    int li = lane >> 2, lj = lane & 3;     // gemm: batches 4*li.., row-group lj
    int kbase = warp * 32;
    int x  = lane & 7;
    int u  = x & 3;
    int half = u >> 1;
    int lb = lane & ~7;
    int bb = tid >> 3;                     // batch 0..31
    int sel = u & 1;
    int active = (x < 4);
    int cid = bb * 4 + u;

    if (active) { c_f[cid] = 0.f; c_b[cid] = 0.f; }

    // pre-gate register pipelines for both dirs
    float pf0 = 0, pf1 = 0, pf2 = 0, pf3 = 0;
    float pb0 = 0, pb1 = 0, pb2 = 0, pb3 = 0;
    int len = 0;
    if (active) {
        len = lengths[bb];
        const float* pp = pre_f + (size_t)bb * G4_ + u_base + u;                    // t=0
        pf0 = __ldg(pp); pf1 = __ldg(pp + 256); pf2 = __ldg(pp + 512); pf3 = __ldg(pp + 768);
        const float* pq = pre_b + ((size_t)(T_ - 1) * B_ + bb) * G4_ + u_base + u;  // t=T-1
        pb0 = __ldg(pq); pb1 = __ldg(pq + 256); pb2 = __ldg(pq + 512); pb3 = __ldg(pq + 768);
    }
    __syncthreads();

    float* hf_glob = hbase;                  // 2 bufs
    float* hb_glob = hbase + 2 * H_ * B_;    // 2 bufs
    int* bar_f = bar;
    int* bar_b = bar + T_;

    for (int s = 0; s < T_; ++s) {
        // ================= PHASE F (t = s) =================
        if (s > 0) {
            if (tid == 0) {
                int v;
                do { asm volatile("ld.acquire.gpu.global.s32 %0, [%1];"
                                  : "=r"(v) : "l"(bar_f + (s - 1)) : "memory"); } while (v < 64);
            }
            __syncthreads();
        }
        {   // per-warp h_f slice load (warp consumes k in [kbase, kbase+32))
            const float* hsrc = hf_glob + (s & 1) * (H_ * B_) + kbase * 32;
            float* hdst = h_f + kbase * 32;
#pragma unroll
            for (int i = 0; i < 8; ++i) {
                int off = (lane + i * 32) * 4;
                *(float4*)(hdst + off) = __ldcg((const float4*)(hsrc + off));
            }
            __syncwarp();
        }
        {   // split-K FFMA2 GEMM fwd
            ull acc2[4][2];
#pragma unroll
            for (int i = 0; i < 4; i++) { acc2[i][0] = 0ull; acc2[i][1] = 0ull; }
#pragma unroll 8
            for (int kk = 0; kk < 32; ++kk) {
                int k = kbase + kk;
                float4 hv = *(const float4*)(h_f + k * 32 + li * 4);
                ulonglong2 wp = *(const ulonglong2*)(w_f + k * 16 + lj * 4);
                ull hd0 = pk2(hv.x, hv.x), hd1 = pk2(hv.y, hv.y);
                ull hd2 = pk2(hv.z, hv.z), hd3 = pk2(hv.w, hv.w);
                acc2[0][0]=ffma2(hd0,wp.x,acc2[0][0]); acc2[0][1]=ffma2(hd0,wp.y,acc2[0][1]);
                acc2[1][0]=ffma2(hd1,wp.x,acc2[1][0]); acc2[1][1]=ffma2(hd1,wp.y,acc2[1][1]);
                acc2[2][0]=ffma2(hd2,wp.x,acc2[2][0]); acc2[2][1]=ffma2(hd2,wp.y,acc2[2][1]);
                acc2[3][0]=ffma2(hd3,wp.x,acc2[3][0]); acc2[3][1]=ffma2(hd3,wp.y,acc2[3][1]);
            }
            ull* rpu = red_u + warp * 256;
#pragma unroll
            for (int i = 0; i < 4; i++)
                *(ulonglong2*)(rpu + (li * 4 + i) * 8 + lj * 2) =
                    make_ulonglong2(acc2[i][0], acc2[i][1]);
        }
        __syncthreads();   // (A_f) partials visible

        {   // reduce + redistribute + update fwd
            ull sacc = red_u[tid];
#pragma unroll
            for (int w = 1; w < 8; ++w) sacc = add2(sacc, red_u[w * 256 + tid]);
            ull vi = __shfl_sync(0xffffffffu, sacc, lb + 0 + half);
            ull vf = __shfl_sync(0xffffffffu, sacc, lb + 2 + half);
            ull vg = __shfl_sync(0xffffffffu, sacc, lb + 4 + half);
            ull vo = __shfl_sync(0xffffffffu, sacc, lb + 6 + half);
            float owf = 0.f;
            if (active) {
                float lo, hi;
                upk2(vi, lo, hi); float gi = (sel ? hi : lo) + pf0;
                upk2(vf, lo, hi); float gf = (sel ? hi : lo) + pf1;
                upk2(vg, lo, hi); float gg = (sel ? hi : lo) + pf2;
                upk2(vo, lo, hi); float go = (sel ? hi : lo) + pf3;
                float c  = c_f[cid];
                float si = 1.f / (1.f + __expf(-gi));
                float sf = 1.f / (1.f + __expf(-gf));
                float so = 1.f / (1.f + __expf(-go));
                float c2 = sf * c + si * tanhf(gg);
                float h2 = so * tanhf(c2);
                float hold = h_f[(u_base + u) * 32 + bb];
                int mvalid = (s < len);
                float hw;
                if (mvalid) { c_f[cid] = c2; hw = h2; owf = h2; }
                else        { hw = hold; owf = 0.f; }
                hf_glob[((s + 1) & 1) * (H_ * B_) + (u_base + u) * 32 + bb] = hw;
            }
            __syncthreads();   // (B_f) h_f stores done
            if (tid == 0 && s + 1 < T_)
                asm volatile("red.release.gpu.global.add.s32 [%0], 1;"
                             :: "l"(bar_f + s) : "memory");
            if (active) {
                xcat[((size_t)s * B_ + bb) * 512 + u_base + u] = owf;
                if (s + 1 < T_) {  // prefetch fwd pre-gates for t=s+1
                    const float* pp = pre_f + ((size_t)(s + 1) * B_ + bb) * G4_ + u_base + u;
                    pf0 = __ldg(pp); pf1 = __ldg(pp + 256);
                    pf2 = __ldg(pp + 512); pf3 = __ldg(pp + 768);
                }
            }
        }

        // ================= PHASE B (t = T-1-s) =================
        int t = T_ - 1 - s;
        if (s > 0) {
            if (tid == 0) {
                int v;
                do { asm volatile("ld.acquire.gpu.global.s32 %0, [%1];"
                                  : "=r"(v) : "l"(bar_b + (s - 1)) : "memory"); } while (v < 64);
            }
            __syncthreads();
        }
        {   // per-warp h_b slice load
            const float* hsrc = hb_glob + (s & 1) * (H_ * B_) + kbase * 32;
            float* hdst = h_b + kbase * 32;
#pragma unroll
            for (int i = 0; i < 8; ++i) {
                int off = (lane + i * 32) * 4;
                *(float4*)(hdst + off) = __ldcg((const float4*)(hsrc + off));
            }
            __syncwarp();
        }
        {   // split-K FFMA2 GEMM bwd
            ull acc2[4][2];
#pragma unroll
            for (int i = 0; i < 4; i++) { acc2[i][0] = 0ull; acc2[i][1] = 0ull; }
#pragma unroll 8
            for (int kk = 0; kk < 32; ++kk) {
                int k = kbase + kk;
                float4 hv = *(const float4*)(h_b + k * 32 + li * 4);
                ulonglong2 wp = *(const ulonglong2*)(w_b + k * 16 + lj * 4);
                ull hd0 = pk2(hv.x, hv.x), hd1 = pk2(hv.y, hv.y);
                ull hd2 = pk2(hv.z, hv.z), hd3 = pk2(hv.w, hv.w);
                acc2[0][0]=ffma2(hd0,wp.x,acc2[0][0]); acc2[0][1]=ffma2(hd0,wp.y,acc2[0][1]);
                acc2[1][0]=ffma2(hd1,wp.x,acc2[1][0]); acc2[1][1]=ffma2(hd1,wp.y,acc2[1][1]);
                acc2[2][0]=ffma2(hd2,wp.x,acc2[2][0]); acc2[2][1]=ffma2(hd2,wp.y,acc2[2][1]);
                acc2[3][0]=ffma2(hd3,wp.x,acc2[3][0]); acc2[3][1]=ffma2(hd3,wp.y,acc2[3][1]);
            }
            ull* rpu = red_u + warp * 256;
#pragma unroll
            for (int i = 0; i < 4; i++)
                *(ulonglong2*)(rpu + (li * 4 + i) * 8 + lj * 2) =
                    make_ulonglong2(acc2[i][0], acc2[i][1]);
        }
        __syncthreads();   // (A_b) partials visible

        {   // reduce + redistribute + update bwd
            ull sacc = red_u[tid];
#pragma unroll
            for (int w = 1; w < 8; ++w) sacc = add2(sacc, red_u[w * 256 + tid]);
            ull vi = __shfl_sync(0xffffffffu, sacc, lb + 0 + half);
            ull vf = __shfl_sync(0xffffffffu, sacc, lb + 2 + half);
            ull vg = __shfl_sync(0xffffffffu, sacc, lb + 4 + half);
            ull vo = __shfl_sync(0xffffffffu, sacc, lb + 6 + half);
            float owb = 0.f;
            if (active) {
                float lo, hi;
                upk2(vi, lo, hi); float gi = (sel ? hi : lo) + pb0;
                upk2(vf, lo, hi); float gf = (sel ? hi : lo) + pb1;
                upk2(vg, lo, hi); float gg = (sel ? hi : lo) + pb2;
                upk2(vo, lo, hi); float go = (sel ? hi : lo) + pb3;
                float c  = c_b[cid];
                float si = 1.f / (1.f + __expf(-gi));
                float sf = 1.f / (1.f + __expf(-gf));
                float so = 1.f / (1.f + __expf(-go));
                float c2 = sf * c + si * tanhf(gg);
                float h2 = so * tanhf(c2);
                float hold = h_b[(u_base + u) * 32 + bb];
                int mvalid = (t < len);
                float hw;
                if (mvalid) { c_b[cid] = c2; hw = h2; owb = h2; }
                else        { hw = hold; owb = 0.f; }
                hb_glob[((s + 1) & 1) * (H_ * B_) + (u_base + u) * 32 + bb] = hw;
            }
            __syncthreads();   // (B_b) h_b stores done
            if (tid == 0 && s + 1 < T_)
                asm volatile("red.release.gpu.global.add.s32 [%0], 1;"
                             :: "l"(bar_b + s) : "memory");
            if (active) {
                xcat[((size_t)t * B_ + bb) * 512 + 256 + u_base + u] = owb;
                if (s + 1 < T_) {  // prefetch bwd pre-gates for t-1
                    const float* pq = pre_b + ((size_t)(t - 1) * B_ + bb) * G4_ + u_base + u;
                    pb0 = __ldg(pq); pb1 = __ldg(pq + 256);
                    pb2 = __ldg(pq + 512); pb3 = __ldg(pq + 768);
                }
            }
        }
    }
}

// ---------------- emit: (8192x512) @ Wout^T(48x512) + bout ----------------
// grid 256, block 256. Also writes transposed output emit (B,T,K).
__global__ void emit_kernel(const float* __restrict__ xcat, const float* __restrict__ Wout,
                            const float* __restrict__ bout, float* __restrict__ emit,
                            float* __restrict__ out_emit) {
    int tid = threadIdx.x;
    int r = tid & 31;
    int cg = tid >> 5;                 // 8 groups x 6 cols
    int m = blockIdx.x * 32 + r;
    int t = m >> 5, b = m & 31;
    const ulonglong2* A = (const ulonglong2*)(xcat + (size_t)m * 512);
    ull accA[6], accB[6];
#pragma unroll
    for (int j = 0; j < 6; ++j) { accA[j] = 0ull; accB[j] = 0ull; }
    for (int k4 = 0; k4 < 128; ++k4) {
        ulonglong2 a = A[k4];
#pragma unroll
        for (int j = 0; j < 6; ++j) {
            int col = cg * 6 + j;
            ulonglong2 w = ((const ulonglong2*)(Wout + (size_t)col * 512))[k4];
            accA[j] = ffma2(a.x, w.x, accA[j]);
            accB[j] = ffma2(a.y, w.y, accB[j]);
        }
    }
#pragma unroll
    for (int j = 0; j < 6; ++j) {
        int col = cg * 6 + j;
        float a0, a1, b0, b1;
        upk2(accA[j], a0, a1); upk2(accB[j], b0, b1);
        float v = a0 + a1 + b0 + b1 + bout[col];
        emit[(size_t)m * K_ + col] = v;
        out_emit[((size_t)b * T_ + t) * K_ + col] = v;
    }
}

// ---------------- CRF per batch: numerator + forward algorithm ----------------
// 192 threads: 4-way split over the j (previous-tag) dimension.
__global__ void crf_kernel(const float* __restrict__ emit, const int* __restrict__ tags,
                           const int* __restrict__ lengths, const float* __restrict__ start_t,
                           const float* __restrict__ end_t, const float* __restrict__ trans,
                           float* __restrict__ part) {
    __shared__ float tr_sh[K_ * K_];
    __shared__ float sc[K_];
    __shared__ float pmax[4][K_];
    __shared__ float psum[4][K_];
    __shared__ float redn[192];
    int b = blockIdx.x, tid = threadIdx.x;
    int k = tid % K_, jj = tid / K_;     // jj in 0..3
    for (int i = tid; i < K_ * K_; i += 192) tr_sh[i] = trans[i];
    int len = lengths[b];
    if (tid < K_) sc[tid] = start_t[tid] + emit[(size_t)b * K_ + tid];
    __syncthreads();
    for (int t = 1; t < len; ++t) {
        float v[12];
        float mx = -1e30f;
#pragma unroll
        for (int jx = 0; jx < 12; ++jx) {
            int j = jj * 12 + jx;
            v[jx] = sc[j] + tr_sh[j * K_ + k];
            mx = fmaxf(mx, v[jx]);
        }
        float ss = 0.f;
#pragma unroll
        for (int jx = 0; jx < 12; ++jx) ss += __expf(v[jx] - mx);
        pmax[jj][k] = mx; psum[jj][k] = ss;
        __syncthreads();
        if (jj == 0) {
            float m0 = pmax[0][k], m1 = pmax[1][k], m2 = pmax[2][k], m3 = pmax[3][k];
            float gm = fmaxf(fmaxf(m0, m1), fmaxf(m2, m3));
            float s = psum[0][k] * __expf(m0 - gm) + psum[1][k] * __expf(m1 - gm)
                    + psum[2][k] * __expf(m2 - gm) + psum[3][k] * __expf(m3 - gm);
            sc[k] = gm + __logf(s) + emit[((size_t)t * B_ + b) * K_ + k];
        }
        __syncthreads();
    }
    // numerator (pure sum over t, parallel)
    float np = 0.f;
    for (int t = tid; t < len; t += 192) {
        int tg = tags[b * T_ + t];
        float e = emit[((size_t)t * B_ + b) * K_ + tg];
        if (t == 0) np += start_t[tg] + e;
        else        np += tr_sh[tags[b * T_ + t - 1] * K_ + tg] + e;
        if (t == len - 1) np += end_t[tg];
    }
    redn[tid] = np;
    __syncthreads();
    if (tid == 0) {
        float num = 0.f;
        for (int i = 0; i < 192; ++i) num += redn[i];
        float mx = -1e30f;
        for (int kk = 0; kk < K_; ++kk) mx = fmaxf(mx, sc[kk] + end_t[kk]);
        float ss = 0.f;
        for (int kk = 0; kk < K_; ++kk) ss += __expf(sc[kk] + end_t[kk] - mx);
        float den = mx + __logf(ss);
        part[b] = num - den;
    }
}

__global__ void finalize_kernel(float* __restrict__ out_loss) {
    if (threadIdx.x == 0) {
        float s = 0.f;
        for (int i = 0; i < B_; ++i) s += g_part[i];
        out_loss[0] = s / (float)B_;
    }
}

// ---------------- host launcher ----------------
extern "C" void kernel_launch(void* const* d_in, const int* in_sizes, int n_in,
                              void* d_out, int out_size) {
    const int*   sentence = (const int*)d_in[0];
    const int*   lengths  = (const int*)d_in[1];
    const int*   tags     = (const int*)d_in[2];
    const float* embed    = (const float*)d_in[3];
    const float* Wih_0f = (const float*)d_in[4];
    const float* Whh_0f = (const float*)d_in[5];
    const float* b_0f   = (const float*)d_in[6];
    const float* Wih_0b = (const float*)d_in[7];
    const float* Whh_0b = (const float*)d_in[8];
    const float* b_0b   = (const float*)d_in[9];
    const float* Wih_1f = (const float*)d_in[10];
    const float* Whh_1f = (const float*)d_in[11];
    const float* b_1f   = (const float*)d_in[12];
    const float* Wih_1b = (const float*)d_in[13];
    const float* Whh_1b = (const float*)d_in[14];
    const float* b_1b   = (const float*)d_in[15];
    const float* Wout   = (const float*)d_in[16];
    const float* bout   = (const float*)d_in[17];
    const float* start_t = (const float*)d_in[18];
    const float* end_t   = (const float*)d_in[19];
    const float* trans   = (const float*)d_in[20];

    float* out = (float*)d_out;
    float* out_emit = out;                       // (B,T,K) = 393216
    float* out_loss = out + (size_t)B_ * T_ * K_;
    float* out_mask = out_loss + 1;              // (B,T)

    const int LSTM_SMEM = 28928 * 4;             // 115712 B
    cudaFuncSetAttribute(lstm_layer, cudaFuncAttributeMaxDynamicSharedMemorySize, LSTM_SMEM);

    float *pre_f, *pre_b, *xcat, *emb, *emit, *hbase;
    cudaGetSymbolAddress((void**)&pre_f, g_pref);
    cudaGetSymbolAddress((void**)&pre_b, g_preb);
    cudaGetSymbolAddress((void**)&xcat,  g_xcat);
    cudaGetSymbolAddress((void**)&emb,   g_emb);
    cudaGetSymbolAddress((void**)&emit,  g_emit);
    cudaGetSymbolAddress((void**)&hbase, g_h);
    int* barp; cudaGetSymbolAddress((void**)&barp, g_bar);
    float* partp; cudaGetSymbolAddress((void**)&partp, g_part);

    dim3 ggrid(16, 64, 2);

    init_kernel<<<32, 256>>>();
    embed_kernel<<<M_, 64>>>(sentence, embed, out_mask);

    gemm_pre<<<ggrid, 256>>>(emb, Wih_0f, Wih_0b, b_0f, b_0b, pre_f, pre_b, E_);
    lstm_layer<<<64, 256, LSTM_SMEM>>>(pre_f, pre_b, Whh_0f, Whh_0b, lengths, xcat,
                                       barp, hbase);

    gemm_pre<<<ggrid, 256>>>(xcat, Wih_1f, Wih_1b, b_1f, b_1b, pre_f, pre_b, 512);
    lstm_layer<<<64, 256, LSTM_SMEM>>>(pre_f, pre_b, Whh_1f, Whh_1b, lengths, xcat,
                                       barp + 2 * T_, hbase + 4 * H_ * B_);

    emit_kernel<<<M_ / 32, 256>>>(xcat, Wout, bout, emit, out_emit);
    crf_kernel<<<B_, 192>>>(emit, tags, lengths, start_t, end_t, trans, partp);
    finalize_kernel<<<1, 32>>>(out_loss);
    (void)in_sizes; (void)n_in; (void)out_size;
}

// round 10
// speedup vs baseline: 1.7682x; 1.7682x over previous
#include <cuda_runtime.h>
#include <math.h>

#define T_ 256
#define B_ 32
#define E_ 256
#define H_ 256
#define K_ 48
#define M_ (T_*B_)      /* 8192 rows (t*B+b) */
#define G4_ 1024        /* 4*H */

typedef unsigned long long ull;

// ---------------- f32x2 packed helpers (FFMA2 path, sm_100+) ----------------
__device__ __forceinline__ ull ffma2(ull a, ull b, ull c) {
    ull d; asm("fma.rn.f32x2 %0, %1, %2, %3;" : "=l"(d) : "l"(a), "l"(b), "l"(c)); return d;
}
__device__ __forceinline__ ull add2(ull a, ull b) {
    ull d; asm("add.rn.f32x2 %0, %1, %2;" : "=l"(d) : "l"(a), "l"(b)); return d;
}
__device__ __forceinline__ ull pk2(float lo, float hi) {
    ull r; asm("mov.b64 %0, {%1, %2};" : "=l"(r) : "f"(lo), "f"(hi)); return r;
}
__device__ __forceinline__ void upk2(ull v, float& lo, float& hi) {
    asm("mov.b64 {%0, %1}, %2;" : "=f"(lo), "=f"(hi) : "l"(v));
}

// ---------------- scratch (device globals; no allocs allowed) ----------------
__device__ float g_emb [M_*E_];           // embedded input, (t*B+b, 256)
__device__ float g_xcat[M_*512];          // concat hf|hb,  (t*B+b, 512)
__device__ float g_pref[(size_t)M_*G4_];  // pre-gates fwd
__device__ float g_preb[(size_t)M_*G4_];  // pre-gates bwd
__device__ float g_emit[M_*K_];           // emit, (t*B+b, 48)
__device__ float g_h   [2*2*2*H_*B_];     // [layer][buf][dir][u*32+b]
__device__ int   g_bar [2*2*T_];          // [layer][dir][step]
__device__ float g_part[B_];
__device__ int   g_rowmap[M_];            // compacted active rows (t*32+b)
__device__ int   g_total[1];              // number of active rows

// ---------------- init: zero h state + barriers each launch ----------------
__global__ void init_kernel() {
    int tid = blockIdx.x * blockDim.x + threadIdx.x;
    int n = blockDim.x * gridDim.x;
    for (int i = tid; i < 2*2*2*H_*B_; i += n) g_h[i] = 0.f;
    for (int i = tid; i < 2*2*T_; i += n) g_bar[i] = 0;
}

// ---------------- active-row map: rows (t,b) with t < lengths[b] ----------
// lengths sorted descending -> active batches for step t are a prefix 0..n_t-1.
__global__ void build_map(const int* __restrict__ lengths) {
    __shared__ int cnt[256];
    int t = threadIdx.x;
    int n = 0;
#pragma unroll
    for (int b = 0; b < B_; ++b) n += (lengths[b] > t) ? 1 : 0;
    cnt[t] = n;
    __syncthreads();
    // inclusive Hillis-Steele scan
    for (int off = 1; off < 256; off <<= 1) {
        int add = (t >= off) ? cnt[t - off] : 0;
        __syncthreads();
        cnt[t] += add;
        __syncthreads();
    }
    int base = cnt[t] - n;
    for (int j = 0; j < n; ++j) g_rowmap[base + j] = t * B_ + j;
    if (t == 255) g_total[0] = cnt[255];
}

// ---------------- embedding gather + mask output ----------------
__global__ void embed_kernel(const int* __restrict__ sentence,
                             const float* __restrict__ embed,
                             float* __restrict__ out_mask) {
    int m = blockIdx.x;             // m = t*B + b
    int t = m >> 5, b = m & 31;
    int tok = sentence[b * T_ + t];
    const float4* src = (const float4*)(embed + (size_t)tok * E_);
    float4* dst = (float4*)(g_emb + (size_t)m * E_);
    dst[threadIdx.x] = src[threadIdx.x];        // 64 threads * float4 = 256
    if (threadIdx.x == 0) out_mask[b * T_ + t] = (tok != 0) ? 1.f : 0.f;
}

// ---------------- SGEMM (FFMA2), masked-row compacted ----------------------
// C[rowmap[r], 1024] = A[rowmap[r], Kd] @ W^T + bias for r < total.
// grid(16, 64, 2), block 256. BM=128, BN=64, BK=8, thread tile 8x4.
__global__ void gemm_pre(const float* __restrict__ A,
                         const float* __restrict__ Wf, const float* __restrict__ Wb,
                         const float* __restrict__ biasf, const float* __restrict__ biasb,
                         float* __restrict__ Cf, float* __restrict__ Cb, int Kd) {
    int total = __ldg(g_total);
    int row0 = blockIdx.y * 128;
    if (row0 >= total) return;

    __shared__ float As[8][128];
    __shared__ float Bs[8][64];
    const float* W    = blockIdx.z ? Wb : Wf;
    const float* bias = blockIdx.z ? biasb : biasf;
    float*       C    = blockIdx.z ? Cb : Cf;

    int tid = threadIdx.x;
    int col0 = blockIdx.x * 64;
    int tr = tid >> 4, tc = tid & 15;      // 16x16 thread grid
    int ar = tid >> 1, ak = (tid & 1) * 4; // A load: 128 rows x 8k
    int wc = tid >> 2, wk = (tid & 3) * 2; // W load: 64 rows x 8k

    int arow = __ldg(g_rowmap + min(row0 + ar, total - 1));
    const float* Arow = A + (size_t)arow * Kd;

    ull acc2[4][4];                        // [row-pair][col]
#pragma unroll
    for (int p = 0; p < 4; p++)
#pragma unroll
        for (int j = 0; j < 4; j++) acc2[p][j] = 0ull;

    for (int k0 = 0; k0 < Kd; k0 += 8) {
        float4 av = *(const float4*)(Arow + k0 + ak);
        float2 wv = *(const float2*)(W + (size_t)(col0 + wc) * Kd + k0 + wk);
        As[ak+0][ar] = av.x; As[ak+1][ar] = av.y; As[ak+2][ar] = av.z; As[ak+3][ar] = av.w;
        Bs[wk+0][wc] = wv.x; Bs[wk+1][wc] = wv.y;
        __syncthreads();
#pragma unroll
        for (int k = 0; k < 8; ++k) {
            ulonglong2 a01 = *(const ulonglong2*)&As[k][tr*8];     // row pairs (0,1),(2,3)
            ulonglong2 a23 = *(const ulonglong2*)&As[k][tr*8+4];   // (4,5),(6,7)
            float4 b4 = *(const float4*)&Bs[k][tc*4];
            ull bd0 = pk2(b4.x, b4.x), bd1 = pk2(b4.y, b4.y);
            ull bd2 = pk2(b4.z, b4.z), bd3 = pk2(b4.w, b4.w);
            acc2[0][0]=ffma2(a01.x,bd0,acc2[0][0]); acc2[0][1]=ffma2(a01.x,bd1,acc2[0][1]);
            acc2[0][2]=ffma2(a01.x,bd2,acc2[0][2]); acc2[0][3]=ffma2(a01.x,bd3,acc2[0][3]);
            acc2[1][0]=ffma2(a01.y,bd0,acc2[1][0]); acc2[1][1]=ffma2(a01.y,bd1,acc2[1][1]);
            acc2[1][2]=ffma2(a01.y,bd2,acc2[1][2]); acc2[1][3]=ffma2(a01.y,bd3,acc2[1][3]);
            acc2[2][0]=ffma2(a23.x,bd0,acc2[2][0]); acc2[2][1]=ffma2(a23.x,bd1,acc2[2][1]);
            acc2[2][2]=ffma2(a23.x,bd2,acc2[2][2]); acc2[2][3]=ffma2(a23.x,bd3,acc2[2][3]);
            acc2[3][0]=ffma2(a23.y,bd0,acc2[3][0]); acc2[3][1]=ffma2(a23.y,bd1,acc2[3][1]);
            acc2[3][2]=ffma2(a23.y,bd2,acc2[3][2]); acc2[3][3]=ffma2(a23.y,bd3,acc2[3][3]);
        }
        __syncthreads();
    }
#pragma unroll
    for (int p = 0; p < 4; p++) {
        int r0 = row0 + tr * 8 + 2 * p;
#pragma unroll
        for (int j = 0; j < 4; j++) {
            int c = col0 + tc * 4 + j;
            float lo, hi; upk2(acc2[p][j], lo, hi);
            float bv = bias[c];
            if (r0 < total) {
                int m0 = __ldg(g_rowmap + r0);
                C[(size_t)m0 * G4_ + c] = lo + bv;
            }
            if (r0 + 1 < total) {
                int m1 = __ldg(g_rowmap + r0 + 1);
                C[(size_t)m1 * G4_ + c] = hi + bv;
            }
        }
    }
}

// ---------------- persistent BiLSTM layer (R5 structure) ----------------
// grid 128 (dir = blk/64), block 256, dyn smem 66048B.
// Block owns 4 hidden units x 32 batches; 8-warp split-K FFMA2 GEMM.
// Barrier: central 64-arrive counter per dir; arrive posted BEFORE the
// xcat store + pre-gate prefetch so those issues overlap the poll.
__global__ void __launch_bounds__(256, 1)
lstm_layer(const float* __restrict__ pre_f, const float* __restrict__ pre_b,
           const float* __restrict__ Whh_f, const float* __restrict__ Whh_b,
           const int* __restrict__ lengths, float* __restrict__ xcat,
           int* __restrict__ bar, float* __restrict__ hbase) {
    extern __shared__ float sm[];
    float* w_sh = sm;                 // [256][16]  (k-major)           4096 f
    float* h_sh = sm + 4096;          // [256][32]  (unit-major)        8192 f
    float* red  = sm + 12288;         // ull [8][256] partials          4096 f
    float* c_sh = sm + 16384;         // [128]                           128 f
    ull* red_u  = (ull*)red;

    int tid = threadIdx.x;
    int dir = blockIdx.x >> 6;
    int blk = blockIdx.x & 63;
    int u_base = blk * 4;
    const float* pre = dir ? pre_b : pre_f;
    const float* Whh = dir ? Whh_b : Whh_f;

    // load weight slice: rows r = gate*4+ui -> global row gate*256 + u_base + ui
    for (int idx = tid; idx < 16 * 256; idx += 256) {
        int r = idx >> 8, k = idx & 255;
        int gate = r >> 2, ui = r & 3;
        w_sh[k * 16 + r] = Whh[(size_t)(gate * 256 + u_base + ui) * 256 + k];
    }

    int warp = tid >> 5, lane = tid & 31;
    int li = lane >> 2, lj = lane & 3;     // gemm: batches 4*li.., row-group lj
    int kbase = warp * 32;
    int x  = lane & 7;
    int u  = x & 3;
    int half = u >> 1;
    int lb = lane & ~7;                    // batch-group base lane
    int bb = tid >> 3;                     // batch 0..31
    int sel = u & 1;                       // which half of the packed pair
    int active = (x < 4);
    int cid = bb * 4 + u;
    int* bar_dir = bar + dir * T_;

    if (active) c_sh[cid] = 0.f;

    // prefetch pre-gates + length (register pipeline)
    float pg0 = 0, pg1 = 0, pg2 = 0, pg3 = 0;
    float pgn0 = 0, pgn1 = 0, pgn2 = 0, pgn3 = 0;
    int len = 0;
    if (active) {
        len = lengths[bb];
        int t0 = dir ? (T_ - 1) : 0;
        const float* pp = pre + ((size_t)t0 * B_ + bb) * G4_ + u_base + u;
        pg0 = __ldg(pp); pg1 = __ldg(pp + 256); pg2 = __ldg(pp + 512); pg3 = __ldg(pp + 768);
    }
    __syncthreads();   // w_sh / c_sh ready

    int cur = 0;
    for (int s = 0; s < T_; ++s) {
        int t = dir ? (T_ - 1 - s) : s;

        // per-warp h slice load (warp consumes k in [kbase, kbase+32))
        {
            const float* hsrc = hbase + (cur * 2 + dir) * (H_ * B_) + kbase * 32;
            float* hdst = h_sh + kbase * 32;
#pragma unroll
            for (int i = 0; i < 8; ++i) {
                int off = (lane + i * 32) * 4;
                float4 v = __ldcg((const float4*)(hsrc + off));
                *(float4*)(hdst + off) = v;
            }
            __syncwarp();
        }

        // split-K FFMA2 GEMM: warp handles k in [kbase, kbase+32)
        ull acc2[4][2];   // [batch i][row-pair jp]
#pragma unroll
        for (int i = 0; i < 4; i++) { acc2[i][0] = 0ull; acc2[i][1] = 0ull; }
#pragma unroll 8
        for (int kk = 0; kk < 32; ++kk) {
            int k = kbase + kk;
            float4 hv = *(const float4*)(h_sh + k * 32 + li * 4);
            ulonglong2 wp = *(const ulonglong2*)(w_sh + k * 16 + lj * 4);
            ull hd0 = pk2(hv.x, hv.x), hd1 = pk2(hv.y, hv.y);
            ull hd2 = pk2(hv.z, hv.z), hd3 = pk2(hv.w, hv.w);
            acc2[0][0]=ffma2(hd0,wp.x,acc2[0][0]); acc2[0][1]=ffma2(hd0,wp.y,acc2[0][1]);
            acc2[1][0]=ffma2(hd1,wp.x,acc2[1][0]); acc2[1][1]=ffma2(hd1,wp.y,acc2[1][1]);
            acc2[2][0]=ffma2(hd2,wp.x,acc2[2][0]); acc2[2][1]=ffma2(hd2,wp.y,acc2[2][1]);
            acc2[3][0]=ffma2(hd3,wp.x,acc2[3][0]); acc2[3][1]=ffma2(hd3,wp.y,acc2[3][1]);
        }
        {
            ull* rpu = red_u + warp * 256;
#pragma unroll
            for (int i = 0; i < 4; i++) {
                *(ulonglong2*)(rpu + (li * 4 + i) * 8 + lj * 2) =
                    make_ulonglong2(acc2[i][0], acc2[i][1]);
            }
        }
        __syncthreads();   // (A) partials visible

        // cross-warp reduce: thread tid owns (batch=tid>>3, row-pair rp=tid&7)
        ull sacc = red_u[tid];
#pragma unroll
        for (int w = 1; w < 8; ++w) sacc = add2(sacc, red_u[w * 256 + tid]);

        // redistribute gates within the 8-lane batch group
        ull vi = __shfl_sync(0xffffffffu, sacc, lb + 0 + half);
        ull vf = __shfl_sync(0xffffffffu, sacc, lb + 2 + half);
        ull vg = __shfl_sync(0xffffffffu, sacc, lb + 4 + half);
        ull vo = __shfl_sync(0xffffffffu, sacc, lb + 6 + half);

        float ow = 0.f;
        if (active) {
            float lo, hi, gi, gf, gg, go;
            upk2(vi, lo, hi); gi = (sel ? hi : lo) + pg0;
            upk2(vf, lo, hi); gf = (sel ? hi : lo) + pg1;
            upk2(vg, lo, hi); gg = (sel ? hi : lo) + pg2;
            upk2(vo, lo, hi); go = (sel ? hi : lo) + pg3;
            float c  = c_sh[cid];
            float si = 1.f / (1.f + __expf(-gi));
            float sf = 1.f / (1.f + __expf(-gf));
            float so = 1.f / (1.f + __expf(-go));
            float c2 = sf * c + si * tanhf(gg);
            float h2 = so * tanhf(c2);
            float hold = h_sh[(u_base + u) * 32 + bb];
            int mvalid = (t < len);
            float hw;
            if (mvalid) { c_sh[cid] = c2; hw = h2; ow = h2; }
            else        { hw = hold; ow = 0.f; }
            hbase[((cur ^ 1) * 2 + dir) * (H_ * B_) + (u_base + u) * 32 + bb] = hw;
        }

        if (s + 1 < T_) {
            __syncthreads();   // (B) all h stores issued
            if (tid == 0)
                asm volatile("red.release.gpu.global.add.s32 [%0], 1;"
                             :: "l"(bar_dir + s) : "memory");
            // overlap xcat store + next pre-gate prefetch with barrier drain
            if (active) {
                xcat[((size_t)t * B_ + bb) * 512 + dir * 256 + u_base + u] = ow;
                int tn = dir ? (T_ - 2 - s) : (s + 1);
                const float* pp = pre + ((size_t)tn * B_ + bb) * G4_ + u_base + u;
                pgn0 = __ldg(pp); pgn1 = __ldg(pp + 256);
                pgn2 = __ldg(pp + 512); pgn3 = __ldg(pp + 768);
            }
            if (tid == 0) {
                int v;
                do {
                    asm volatile("ld.acquire.gpu.global.s32 %0, [%1];"
                                 : "=r"(v) : "l"(bar_dir + s) : "memory");
                } while (v < 64);
            }
            __syncthreads();   // (C) release the block
        } else if (active) {
            xcat[((size_t)t * B_ + bb) * 512 + dir * 256 + u_base + u] = ow;
        }
        pg0 = pgn0; pg1 = pgn1; pg2 = pgn2; pg3 = pgn3;
        cur ^= 1;
    }
}

// ---------------- emit: (8192x512) @ Wout^T(48x512) + bout ----------------
// grid 256, block 256. Also writes transposed output emit (B,T,K).
__global__ void emit_kernel(const float* __restrict__ xcat, const float* __restrict__ Wout,
                            const float* __restrict__ bout, float* __restrict__ emit,
                            float* __restrict__ out_emit) {
    int tid = threadIdx.x;
    int r = tid & 31;
    int cg = tid >> 5;                 // 8 groups x 6 cols
    int m = blockIdx.x * 32 + r;
    int t = m >> 5, b = m & 31;
    const ulonglong2* A = (const ulonglong2*)(xcat + (size_t)m * 512);
    ull accA[6], accB[6];
#pragma unroll
    for (int j = 0; j < 6; ++j) { accA[j] = 0ull; accB[j] = 0ull; }
    for (int k4 = 0; k4 < 128; ++k4) {
        ulonglong2 a = A[k4];
#pragma unroll
        for (int j = 0; j < 6; ++j) {
            int col = cg * 6 + j;
            ulonglong2 w = ((const ulonglong2*)(Wout + (size_t)col * 512))[k4];
            accA[j] = ffma2(a.x, w.x, accA[j]);
            accB[j] = ffma2(a.y, w.y, accB[j]);
        }
    }
#pragma unroll
    for (int j = 0; j < 6; ++j) {
        int col = cg * 6 + j;
        float a0, a1, b0, b1;
        upk2(accA[j], a0, a1); upk2(accB[j], b0, b1);
        float v = a0 + a1 + b0 + b1 + bout[col];
        emit[(size_t)m * K_ + col] = v;
        out_emit[((size_t)b * T_ + t) * K_ + col] = v;
    }
}

// ---------------- CRF per batch: numerator + forward algorithm ----------------
// 192 threads: 4-way split over the j (previous-tag) dimension.
__global__ void crf_kernel(const float* __restrict__ emit, const int* __restrict__ tags,
                           const int* __restrict__ lengths, const float* __restrict__ start_t,
                           const float* __restrict__ end_t, const float* __restrict__ trans,
                           float* __restrict__ part) {
    __shared__ float tr_sh[K_ * K_];
    __shared__ float sc[K_];
    __shared__ float pmax[4][K_];
    __shared__ float psum[4][K_];
    __shared__ float redn[192];
    int b = blockIdx.x, tid = threadIdx.x;
    int k = tid % K_, jj = tid / K_;     // jj in 0..3
    for (int i = tid; i < K_ * K_; i += 192) tr_sh[i] = trans[i];
    int len = lengths[b];
    if (tid < K_) sc[tid] = start_t[tid] + emit[(size_t)b * K_ + tid];
    __syncthreads();
    for (int t = 1; t < len; ++t) {
        float v[12];
        float mx = -1e30f;
#pragma unroll
        for (int jx = 0; jx < 12; ++jx) {
            int j = jj * 12 + jx;
            v[jx] = sc[j] + tr_sh[j * K_ + k];
            mx = fmaxf(mx, v[jx]);
        }
        float ss = 0.f;
#pragma unroll
        for (int jx = 0; jx < 12; ++jx) ss += __expf(v[jx] - mx);
        pmax[jj][k] = mx; psum[jj][k] = ss;
        __syncthreads();
        if (jj == 0) {
            float m0 = pmax[0][k], m1 = pmax[1][k], m2 = pmax[2][k], m3 = pmax[3][k];
            float gm = fmaxf(fmaxf(m0, m1), fmaxf(m2, m3));
            float s = psum[0][k] * __expf(m0 - gm) + psum[1][k] * __expf(m1 - gm)
                    + psum[2][k] * __expf(m2 - gm) + psum[3][k] * __expf(m3 - gm);
            sc[k] = gm + __logf(s) + emit[((size_t)t * B_ + b) * K_ + k];
        }
        __syncthreads();
    }
    // numerator (pure sum over t, parallel)
    float np = 0.f;
    for (int t = tid; t < len; t += 192) {
        int tg = tags[b * T_ + t];
        float e = emit[((size_t)t * B_ + b) * K_ + tg];
        if (t == 0) np += start_t[tg] + e;
        else        np += tr_sh[tags[b * T_ + t - 1] * K_ + tg] + e;
        if (t == len - 1) np += end_t[tg];
    }
    redn[tid] = np;
    __syncthreads();
    if (tid == 0) {
        float num = 0.f;
        for (int i = 0; i < 192; ++i) num += redn[i];
        float mx = -1e30f;
        for (int kk = 0; kk < K_; ++kk) mx = fmaxf(mx, sc[kk] + end_t[kk]);
        float ss = 0.f;
        for (int kk = 0; kk < K_; ++kk) ss += __expf(sc[kk] + end_t[kk] - mx);
        float den = mx + __logf(ss);
        part[b] = num - den;
    }
}

__global__ void finalize_kernel(float* __restrict__ out_loss) {
    if (threadIdx.x == 0) {
        float s = 0.f;
        for (int i = 0; i < B_; ++i) s += g_part[i];
        out_loss[0] = s / (float)B_;
    }
}

// ---------------- host launcher ----------------
extern "C" void kernel_launch(void* const* d_in, const int* in_sizes, int n_in,
                              void* d_out, int out_size) {
    const int*   sentence = (const int*)d_in[0];
    const int*   lengths  = (const int*)d_in[1];
    const int*   tags     = (const int*)d_in[2];
    const float* embed    = (const float*)d_in[3];
    const float* Wih_0f = (const float*)d_in[4];
    const float* Whh_0f = (const float*)d_in[5];
    const float* b_0f   = (const float*)d_in[6];
    const float* Wih_0b = (const float*)d_in[7];
    const float* Whh_0b = (const float*)d_in[8];
    const float* b_0b   = (const float*)d_in[9];
    const float* Wih_1f = (const float*)d_in[10];
    const float* Whh_1f = (const float*)d_in[11];
    const float* b_1f   = (const float*)d_in[12];
    const float* Wih_1b = (const float*)d_in[13];
    const float* Whh_1b = (const float*)d_in[14];
    const float* b_1b   = (const float*)d_in[15];
    const float* Wout   = (const float*)d_in[16];
    const float* bout   = (const float*)d_in[17];
    const float* start_t = (const float*)d_in[18];
    const float* end_t   = (const float*)d_in[19];
    const float* trans   = (const float*)d_in[20];

    float* out = (float*)d_out;
    float* out_emit = out;                       // (B,T,K) = 393216
    float* out_loss = out + (size_t)B_ * T_ * K_;
    float* out_mask = out_loss + 1;              // (B,T)

    const int LSTM_SMEM = 16512 * 4;             // 66048 B
    cudaFuncSetAttribute(lstm_layer, cudaFuncAttributeMaxDynamicSharedMemorySize, LSTM_SMEM);

    float *pre_f, *pre_b, *xcat, *emb, *emit, *hbase;
    cudaGetSymbolAddress((void**)&pre_f, g_pref);
    cudaGetSymbolAddress((void**)&pre_b, g_preb);
    cudaGetSymbolAddress((void**)&xcat,  g_xcat);
    cudaGetSymbolAddress((void**)&emb,   g_emb);
    cudaGetSymbolAddress((void**)&emit,  g_emit);
    cudaGetSymbolAddress((void**)&hbase, g_h);
    int* barp; cudaGetSymbolAddress((void**)&barp, g_bar);
    float* partp; cudaGetSymbolAddress((void**)&partp, g_part);

    dim3 ggrid(16, 64, 2);

    init_kernel<<<32, 256>>>();
    build_map<<<1, 256>>>(lengths);
    embed_kernel<<<M_, 64>>>(sentence, embed, out_mask);

    gemm_pre<<<ggrid, 256>>>(emb, Wih_0f, Wih_0b, b_0f, b_0b, pre_f, pre_b, E_);
    lstm_layer<<<128, 256, LSTM_SMEM>>>(pre_f, pre_b, Whh_0f, Whh_0b, lengths, xcat,
                                        barp, hbase);

    gemm_pre<<<ggrid, 256>>>(xcat, Wih_1f, Wih_1b, b_1f, b_1b, pre_f, pre_b, 512);
    lstm_layer<<<128, 256, LSTM_SMEM>>>(pre_f, pre_b, Whh_1f, Whh_1b, lengths, xcat,
                                        barp + 2 * T_, hbase + 2 * 2 * H_ * B_);

    emit_kernel<<<M_ / 32, 256>>>(xcat, Wout, bout, emit, out_emit);
    crf_kernel<<<B_, 192>>>(emit, tags, lengths, start_t, end_t, trans, partp);
    finalize_kernel<<<1, 32>>>(out_loss);
    (void)in_sizes; (void)n_in; (void)out_size;
}

// round 11
// speedup vs baseline: 1.7777x; 1.0054x over previous
#include <cuda_runtime.h>
#include <math.h>

#define T_ 256
#define B_ 32
#define E_ 256
#define H_ 256
#define K_ 48
#define M_ (T_*B_)      /* 8192 rows (t*B+b) */
#define G4_ 1024        /* 4*H */

typedef unsigned long long ull;

// ---------------- f32x2 packed helpers (FFMA2 path, sm_100+) ----------------
__device__ __forceinline__ ull ffma2(ull a, ull b, ull c) {
    ull d; asm("fma.rn.f32x2 %0, %1, %2, %3;" : "=l"(d) : "l"(a), "l"(b), "l"(c)); return d;
}
__device__ __forceinline__ ull add2(ull a, ull b) {
    ull d; asm("add.rn.f32x2 %0, %1, %2;" : "=l"(d) : "l"(a), "l"(b)); return d;
}
__device__ __forceinline__ ull pk2(float lo, float hi) {
    ull r; asm("mov.b64 %0, {%1, %2};" : "=l"(r) : "f"(lo), "f"(hi)); return r;
}
__device__ __forceinline__ void upk2(ull v, float& lo, float& hi) {
    asm("mov.b64 {%0, %1}, %2;" : "=f"(lo), "=f"(hi) : "l"(v));
}

// ---------------- scratch (device globals; no allocs allowed) ----------------
__device__ float g_emb [M_*E_];           // embedded input, (t*B+b, 256)
__device__ float g_xcat[M_*512];          // concat hf|hb,  (t*B+b, 512)
__device__ float g_pref[(size_t)M_*G4_];  // pre-gates fwd
__device__ float g_preb[(size_t)M_*G4_];  // pre-gates bwd
__device__ float g_emit[M_*K_];           // emit, (t*B+b, 48)
__device__ float g_h   [2*2*2*H_*B_];     // [layer][buf][dir][u*32+b]
__device__ int   g_bar [2*2*T_];          // [layer][dir][step]
__device__ float g_part[B_];
__device__ int   g_rowmap[M_];            // compacted active rows (t*32+b)
__device__ int   g_total[1];              // number of active rows

// ---------------- init: zero h state + barriers each launch ----------------
__global__ void init_kernel() {
    int tid = blockIdx.x * blockDim.x + threadIdx.x;
    int n = blockDim.x * gridDim.x;
    for (int i = tid; i < 2*2*2*H_*B_; i += n) g_h[i] = 0.f;
    for (int i = tid; i < 2*2*T_; i += n) g_bar[i] = 0;
}

// ---------------- active-row map: rows (t,b) with t < lengths[b] ----------
// lengths sorted descending -> active batches for step t are a prefix 0..n_t-1.
__global__ void build_map(const int* __restrict__ lengths) {
    __shared__ int cnt[256];
    int t = threadIdx.x;
    int n = 0;
#pragma unroll
    for (int b = 0; b < B_; ++b) n += (lengths[b] > t) ? 1 : 0;
    cnt[t] = n;
    __syncthreads();
    // inclusive Hillis-Steele scan
    for (int off = 1; off < 256; off <<= 1) {
        int add = (t >= off) ? cnt[t - off] : 0;
        __syncthreads();
        cnt[t] += add;
        __syncthreads();
    }
    int base = cnt[t] - n;
    for (int j = 0; j < n; ++j) g_rowmap[base + j] = t * B_ + j;
    if (t == 255) g_total[0] = cnt[255];
}

// ---------------- embedding gather + mask output ----------------
__global__ void embed_kernel(const int* __restrict__ sentence,
                             const float* __restrict__ embed,
                             float* __restrict__ out_mask) {
    int m = blockIdx.x;             // m = t*B + b
    int t = m >> 5, b = m & 31;
    int tok = sentence[b * T_ + t];
    const float4* src = (const float4*)(embed + (size_t)tok * E_);
    float4* dst = (float4*)(g_emb + (size_t)m * E_);
    dst[threadIdx.x] = src[threadIdx.x];        // 64 threads * float4 = 256
    if (threadIdx.x == 0) out_mask[b * T_ + t] = (tok != 0) ? 1.f : 0.f;
}

// ---------------- SGEMM (FFMA2), masked-row compacted ----------------------
// C[rowmap[r], 1024] = A[rowmap[r], Kd] @ W^T + bias for r < total.
// grid(16, 64, 2), block 256. BM=128, BN=64, BK=8, thread tile 8x4.
__global__ void gemm_pre(const float* __restrict__ A,
                         const float* __restrict__ Wf, const float* __restrict__ Wb,
                         const float* __restrict__ biasf, const float* __restrict__ biasb,
                         float* __restrict__ Cf, float* __restrict__ Cb, int Kd) {
    int total = __ldg(g_total);
    int row0 = blockIdx.y * 128;
    if (row0 >= total) return;

    __shared__ float As[8][128];
    __shared__ float Bs[8][64];
    const float* W    = blockIdx.z ? Wb : Wf;
    const float* bias = blockIdx.z ? biasb : biasf;
    float*       C    = blockIdx.z ? Cb : Cf;

    int tid = threadIdx.x;
    int col0 = blockIdx.x * 64;
    int tr = tid >> 4, tc = tid & 15;      // 16x16 thread grid
    int ar = tid >> 1, ak = (tid & 1) * 4; // A load: 128 rows x 8k
    int wc = tid >> 2, wk = (tid & 3) * 2; // W load: 64 rows x 8k

    int arow = __ldg(g_rowmap + min(row0 + ar, total - 1));
    const float* Arow = A + (size_t)arow * Kd;

    ull acc2[4][4];                        // [row-pair][col]
#pragma unroll
    for (int p = 0; p < 4; p++)
#pragma unroll
        for (int j = 0; j < 4; j++) acc2[p][j] = 0ull;

    for (int k0 = 0; k0 < Kd; k0 += 8) {
        float4 av = *(const float4*)(Arow + k0 + ak);
        float2 wv = *(const float2*)(W + (size_t)(col0 + wc) * Kd + k0 + wk);
        As[ak+0][ar] = av.x; As[ak+1][ar] = av.y; As[ak+2][ar] = av.z; As[ak+3][ar] = av.w;
        Bs[wk+0][wc] = wv.x; Bs[wk+1][wc] = wv.y;
        __syncthreads();
#pragma unroll
        for (int k = 0; k < 8; ++k) {
            ulonglong2 a01 = *(const ulonglong2*)&As[k][tr*8];     // row pairs (0,1),(2,3)
            ulonglong2 a23 = *(const ulonglong2*)&As[k][tr*8+4];   // (4,5),(6,7)
            float4 b4 = *(const float4*)&Bs[k][tc*4];
            ull bd0 = pk2(b4.x, b4.x), bd1 = pk2(b4.y, b4.y);
            ull bd2 = pk2(b4.z, b4.z), bd3 = pk2(b4.w, b4.w);
            acc2[0][0]=ffma2(a01.x,bd0,acc2[0][0]); acc2[0][1]=ffma2(a01.x,bd1,acc2[0][1]);
            acc2[0][2]=ffma2(a01.x,bd2,acc2[0][2]); acc2[0][3]=ffma2(a01.x,bd3,acc2[0][3]);
            acc2[1][0]=ffma2(a01.y,bd0,acc2[1][0]); acc2[1][1]=ffma2(a01.y,bd1,acc2[1][1]);
            acc2[1][2]=ffma2(a01.y,bd2,acc2[1][2]); acc2[1][3]=ffma2(a01.y,bd3,acc2[1][3]);
            acc2[2][0]=ffma2(a23.x,bd0,acc2[2][0]); acc2[2][1]=ffma2(a23.x,bd1,acc2[2][1]);
            acc2[2][2]=ffma2(a23.x,bd2,acc2[2][2]); acc2[2][3]=ffma2(a23.x,bd3,acc2[2][3]);
            acc2[3][0]=ffma2(a23.y,bd0,acc2[3][0]); acc2[3][1]=ffma2(a23.y,bd1,acc2[3][1]);
            acc2[3][2]=ffma2(a23.y,bd2,acc2[3][2]); acc2[3][3]=ffma2(a23.y,bd3,acc2[3][3]);
        }
        __syncthreads();
    }
#pragma unroll
    for (int p = 0; p < 4; p++) {
        int r0 = row0 + tr * 8 + 2 * p;
#pragma unroll
        for (int j = 0; j < 4; j++) {
            int c = col0 + tc * 4 + j;
            float lo, hi; upk2(acc2[p][j], lo, hi);
            float bv = bias[c];
            if (r0 < total) {
                int m0 = __ldg(g_rowmap + r0);
                C[(size_t)m0 * G4_ + c] = lo + bv;
            }
            if (r0 + 1 < total) {
                int m1 = __ldg(g_rowmap + r0 + 1);
                C[(size_t)m1 * G4_ + c] = hi + bv;
            }
        }
    }
}

// ---------------- persistent BiLSTM layer (R5 structure) ----------------
// grid 128 (dir = blk/64), block 256, dyn smem 66048B.
// Block owns 4 hidden units x 32 batches; 8-warp split-K FFMA2 GEMM.
// Barrier: central 64-arrive counter per dir; arrive posted BEFORE the
// xcat store + pre-gate prefetch so those issues overlap the poll.
__global__ void __launch_bounds__(256, 1)
lstm_layer(const float* __restrict__ pre_f, const float* __restrict__ pre_b,
           const float* __restrict__ Whh_f, const float* __restrict__ Whh_b,
           const int* __restrict__ lengths, float* __restrict__ xcat,
           int* __restrict__ bar, float* __restrict__ hbase) {
    extern __shared__ float sm[];
    float* w_sh = sm;                 // [256][16]  (k-major)           4096 f
    float* h_sh = sm + 4096;          // [256][32]  (unit-major)        8192 f
    float* red  = sm + 12288;         // ull [8][256] partials          4096 f
    float* c_sh = sm + 16384;         // [128]                           128 f
    ull* red_u  = (ull*)red;

    int tid = threadIdx.x;
    int dir = blockIdx.x >> 6;
    int blk = blockIdx.x & 63;
    int u_base = blk * 4;
    const float* pre = dir ? pre_b : pre_f;
    const float* Whh = dir ? Whh_b : Whh_f;

    // load weight slice: rows r = gate*4+ui -> global row gate*256 + u_base + ui
    for (int idx = tid; idx < 16 * 256; idx += 256) {
        int r = idx >> 8, k = idx & 255;
        int gate = r >> 2, ui = r & 3;
        w_sh[k * 16 + r] = Whh[(size_t)(gate * 256 + u_base + ui) * 256 + k];
    }

    int warp = tid >> 5, lane = tid & 31;
    int li = lane >> 2, lj = lane & 3;     // gemm: batches 4*li.., row-group lj
    int kbase = warp * 32;
    int x  = lane & 7;
    int u  = x & 3;
    int half = u >> 1;
    int lb = lane & ~7;                    // batch-group base lane
    int bb = tid >> 3;                     // batch 0..31
    int sel = u & 1;                       // which half of the packed pair
    int active = (x < 4);
    int cid = bb * 4 + u;
    int* bar_dir = bar + dir * T_;

    if (active) c_sh[cid] = 0.f;

    // prefetch pre-gates + length (register pipeline)
    float pg0 = 0, pg1 = 0, pg2 = 0, pg3 = 0;
    float pgn0 = 0, pgn1 = 0, pgn2 = 0, pgn3 = 0;
    int len = 0;
    if (active) {
        len = lengths[bb];
        int t0 = dir ? (T_ - 1) : 0;
        const float* pp = pre + ((size_t)t0 * B_ + bb) * G4_ + u_base + u;
        pg0 = __ldg(pp); pg1 = __ldg(pp + 256); pg2 = __ldg(pp + 512); pg3 = __ldg(pp + 768);
    }
    __syncthreads();   // w_sh / c_sh ready

    int cur = 0;
    for (int s = 0; s < T_; ++s) {
        int t = dir ? (T_ - 1 - s) : s;

        // per-warp h slice load (warp consumes k in [kbase, kbase+32))
        {
            const float* hsrc = hbase + (cur * 2 + dir) * (H_ * B_) + kbase * 32;
            float* hdst = h_sh + kbase * 32;
#pragma unroll
            for (int i = 0; i < 8; ++i) {
                int off = (lane + i * 32) * 4;
                float4 v = __ldcg((const float4*)(hsrc + off));
                *(float4*)(hdst + off) = v;
            }
            __syncwarp();
        }

        // split-K FFMA2 GEMM: warp handles k in [kbase, kbase+32)
        ull acc2[4][2];   // [batch i][row-pair jp]
#pragma unroll
        for (int i = 0; i < 4; i++) { acc2[i][0] = 0ull; acc2[i][1] = 0ull; }
#pragma unroll 8
        for (int kk = 0; kk < 32; ++kk) {
            int k = kbase + kk;
            float4 hv = *(const float4*)(h_sh + k * 32 + li * 4);
            ulonglong2 wp = *(const ulonglong2*)(w_sh + k * 16 + lj * 4);
            ull hd0 = pk2(hv.x, hv.x), hd1 = pk2(hv.y, hv.y);
            ull hd2 = pk2(hv.z, hv.z), hd3 = pk2(hv.w, hv.w);
            acc2[0][0]=ffma2(hd0,wp.x,acc2[0][0]); acc2[0][1]=ffma2(hd0,wp.y,acc2[0][1]);
            acc2[1][0]=ffma2(hd1,wp.x,acc2[1][0]); acc2[1][1]=ffma2(hd1,wp.y,acc2[1][1]);
            acc2[2][0]=ffma2(hd2,wp.x,acc2[2][0]); acc2[2][1]=ffma2(hd2,wp.y,acc2[2][1]);
            acc2[3][0]=ffma2(hd3,wp.x,acc2[3][0]); acc2[3][1]=ffma2(hd3,wp.y,acc2[3][1]);
        }
        {
            ull* rpu = red_u + warp * 256;
#pragma unroll
            for (int i = 0; i < 4; i++) {
                *(ulonglong2*)(rpu + (li * 4 + i) * 8 + lj * 2) =
                    make_ulonglong2(acc2[i][0], acc2[i][1]);
            }
        }
        __syncthreads();   // (A) partials visible

        // cross-warp reduce: thread tid owns (batch=tid>>3, row-pair rp=tid&7)
        ull sacc = red_u[tid];
#pragma unroll
        for (int w = 1; w < 8; ++w) sacc = add2(sacc, red_u[w * 256 + tid]);

        // redistribute gates within the 8-lane batch group
        ull vi = __shfl_sync(0xffffffffu, sacc, lb + 0 + half);
        ull vf = __shfl_sync(0xffffffffu, sacc, lb + 2 + half);
        ull vg = __shfl_sync(0xffffffffu, sacc, lb + 4 + half);
        ull vo = __shfl_sync(0xffffffffu, sacc, lb + 6 + half);

        float ow = 0.f;
        if (active) {
            float lo, hi, gi, gf, gg, go;
            upk2(vi, lo, hi); gi = (sel ? hi : lo) + pg0;
            upk2(vf, lo, hi); gf = (sel ? hi : lo) + pg1;
            upk2(vg, lo, hi); gg = (sel ? hi : lo) + pg2;
            upk2(vo, lo, hi); go = (sel ? hi : lo) + pg3;
            float c  = c_sh[cid];
            float si = 1.f / (1.f + __expf(-gi));
            float sf = 1.f / (1.f + __expf(-gf));
            float so = 1.f / (1.f + __expf(-go));
            float c2 = sf * c + si * tanhf(gg);
            float h2 = so * tanhf(c2);
            float hold = h_sh[(u_base + u) * 32 + bb];
            int mvalid = (t < len);
            float hw;
            if (mvalid) { c_sh[cid] = c2; hw = h2; ow = h2; }
            else        { hw = hold; ow = 0.f; }
            hbase[((cur ^ 1) * 2 + dir) * (H_ * B_) + (u_base + u) * 32 + bb] = hw;
        }

        if (s + 1 < T_) {
            __syncthreads();   // (B) all h stores issued
            if (tid == 0)
                asm volatile("red.release.gpu.global.add.s32 [%0], 1;"
                             :: "l"(bar_dir + s) : "memory");
            // overlap xcat store + next pre-gate prefetch with barrier drain
            if (active) {
                xcat[((size_t)t * B_ + bb) * 512 + dir * 256 + u_base + u] = ow;
                int tn = dir ? (T_ - 2 - s) : (s + 1);
                const float* pp = pre + ((size_t)tn * B_ + bb) * G4_ + u_base + u;
                pgn0 = __ldg(pp); pgn1 = __ldg(pp + 256);
                pgn2 = __ldg(pp + 512); pgn3 = __ldg(pp + 768);
            }
            if (tid == 0) {
                int v;
                do {
                    asm volatile("ld.acquire.gpu.global.s32 %0, [%1];"
                                 : "=r"(v) : "l"(bar_dir + s) : "memory");
                } while (v < 64);
            }
            __syncthreads();   // (C) release the block
        } else if (active) {
            xcat[((size_t)t * B_ + bb) * 512 + dir * 256 + u_base + u] = ow;
        }
        pg0 = pgn0; pg1 = pgn1; pg2 = pgn2; pg3 = pgn3;
        cur ^= 1;
    }
}

// ---------------- emit: (8192x512) @ Wout^T(48x512) + bout ----------------
// grid 256, block 256. Also writes transposed output emit (B,T,K).
__global__ void emit_kernel(const float* __restrict__ xcat, const float* __restrict__ Wout,
                            const float* __restrict__ bout, float* __restrict__ emit,
                            float* __restrict__ out_emit) {
    int tid = threadIdx.x;
    int r = tid & 31;
    int cg = tid >> 5;                 // 8 groups x 6 cols
    int m = blockIdx.x * 32 + r;
    int t = m >> 5, b = m & 31;
    const ulonglong2* A = (const ulonglong2*)(xcat + (size_t)m * 512);
    ull accA[6], accB[6];
#pragma unroll
    for (int j = 0; j < 6; ++j) { accA[j] = 0ull; accB[j] = 0ull; }
    for (int k4 = 0; k4 < 128; ++k4) {
        ulonglong2 a = A[k4];
#pragma unroll
        for (int j = 0; j < 6; ++j) {
            int col = cg * 6 + j;
            ulonglong2 w = ((const ulonglong2*)(Wout + (size_t)col * 512))[k4];
            accA[j] = ffma2(a.x, w.x, accA[j]);
            accB[j] = ffma2(a.y, w.y, accB[j]);
        }
    }
#pragma unroll
    for (int j = 0; j < 6; ++j) {
        int col = cg * 6 + j;
        float a0, a1, b0, b1;
        upk2(accA[j], a0, a1); upk2(accB[j], b0, b1);
        float v = a0 + a1 + b0 + b1 + bout[col];
        emit[(size_t)m * K_ + col] = v;
        out_emit[((size_t)b * T_ + t) * K_ + col] = v;
    }
}

// ---------------- CRF per batch: numerator + forward algorithm ----------------
// 192 threads: 4-way split over the j (previous-tag) dimension.
__global__ void crf_kernel(const float* __restrict__ emit, const int* __restrict__ tags,
                           const int* __restrict__ lengths, const float* __restrict__ start_t,
                           const float* __restrict__ end_t, const float* __restrict__ trans,
                           float* __restrict__ part) {
    __shared__ float tr_sh[K_ * K_];
    __shared__ float sc[K_];
    __shared__ float pmax[4][K_];
    __shared__ float psum[4][K_];
    __shared__ float redn[192];
    int b = blockIdx.x, tid = threadIdx.x;
    int k = tid % K_, jj = tid / K_;     // jj in 0..3
    for (int i = tid; i < K_ * K_; i += 192) tr_sh[i] = trans[i];
    int len = lengths[b];
    if (tid < K_) sc[tid] = start_t[tid] + emit[(size_t)b * K_ + tid];
    __syncthreads();
    for (int t = 1; t < len; ++t) {
        float v[12];
        float mx = -1e30f;
#pragma unroll
        for (int jx = 0; jx < 12; ++jx) {
            int j = jj * 12 + jx;
            v[jx] = sc[j] + tr_sh[j * K_ + k];
            mx = fmaxf(mx, v[jx]);
        }
        float ss = 0.f;
#pragma unroll
        for (int jx = 0; jx < 12; ++jx) ss += __expf(v[jx] - mx);
        pmax[jj][k] = mx; psum[jj][k] = ss;
        __syncthreads();
        if (jj == 0) {
            float m0 = pmax[0][k], m1 = pmax[1][k], m2 = pmax[2][k], m3 = pmax[3][k];
            float gm = fmaxf(fmaxf(m0, m1), fmaxf(m2, m3));
            float s = psum[0][k] * __expf(m0 - gm) + psum[1][k] * __expf(m1 - gm)
                    + psum[2][k] * __expf(m2 - gm) + psum[3][k] * __expf(m3 - gm);
            sc[k] = gm + __logf(s) + emit[((size_t)t * B_ + b) * K_ + k];
        }
        __syncthreads();
    }
    // numerator (pure sum over t, parallel)
    float np = 0.f;
    for (int t = tid; t < len; t += 192) {
        int tg = tags[b * T_ + t];
        float e = emit[((size_t)t * B_ + b) * K_ + tg];
        if (t == 0) np += start_t[tg] + e;
        else        np += tr_sh[tags[b * T_ + t - 1] * K_ + tg] + e;
        if (t == len - 1) np += end_t[tg];
    }
    redn[tid] = np;
    __syncthreads();
    if (tid == 0) {
        float num = 0.f;
        for (int i = 0; i < 192; ++i) num += redn[i];
        float mx = -1e30f;
        for (int kk = 0; kk < K_; ++kk) mx = fmaxf(mx, sc[kk] + end_t[kk]);
        float ss = 0.f;
        for (int kk = 0; kk < K_; ++kk) ss += __expf(sc[kk] + end_t[kk] - mx);
        float den = mx + __logf(ss);
        part[b] = num - den;
    }
}

__global__ void finalize_kernel(float* __restrict__ out_loss) {
    if (threadIdx.x == 0) {
        float s = 0.f;
        for (int i = 0; i < B_; ++i) s += g_part[i];
        out_loss[0] = s / (float)B_;
    }
}

// ---------------- host launcher ----------------
extern "C" void kernel_launch(void* const* d_in, const int* in_sizes, int n_in,
                              void* d_out, int out_size) {
    const int*   sentence = (const int*)d_in[0];
    const int*   lengths  = (const int*)d_in[1];
    const int*   tags     = (const int*)d_in[2];
    const float* embed    = (const float*)d_in[3];
    const float* Wih_0f = (const float*)d_in[4];
    const float* Whh_0f = (const float*)d_in[5];
    const float* b_0f   = (const float*)d_in[6];
    const float* Wih_0b = (const float*)d_in[7];
    const float* Whh_0b = (const float*)d_in[8];
    const float* b_0b   = (const float*)d_in[9];
    const float* Wih_1f = (const float*)d_in[10];
    const float* Whh_1f = (const float*)d_in[11];
    const float* b_1f   = (const float*)d_in[12];
    const float* Wih_1b = (const float*)d_in[13];
    const float* Whh_1b = (const float*)d_in[14];
    const float* b_1b   = (const float*)d_in[15];
    const float* Wout   = (const float*)d_in[16];
    const float* bout   = (const float*)d_in[17];
    const float* start_t = (const float*)d_in[18];
    const float* end_t   = (const float*)d_in[19];
    const float* trans   = (const float*)d_in[20];

    float* out = (float*)d_out;
    float* out_emit = out;                       // (B,T,K) = 393216
    float* out_loss = out + (size_t)B_ * T_ * K_;
    float* out_mask = out_loss + 1;              // (B,T)

    const int LSTM_SMEM = 16512 * 4;             // 66048 B
    cudaFuncSetAttribute(lstm_layer, cudaFuncAttributeMaxDynamicSharedMemorySize, LSTM_SMEM);

    float *pre_f, *pre_b, *xcat, *emb, *emit, *hbase;
    cudaGetSymbolAddress((void**)&pre_f, g_pref);
    cudaGetSymbolAddress((void**)&pre_b, g_preb);
    cudaGetSymbolAddress((void**)&xcat,  g_xcat);
    cudaGetSymbolAddress((void**)&emb,   g_emb);
    cudaGetSymbolAddress((void**)&emit,  g_emit);
    cudaGetSymbolAddress((void**)&hbase, g_h);
    int* barp; cudaGetSymbolAddress((void**)&barp, g_bar);
    float* partp; cudaGetSymbolAddress((void**)&partp, g_part);

    dim3 ggrid(16, 64, 2);

    init_kernel<<<32, 256>>>();
    build_map<<<1, 256>>>(lengths);
    embed_kernel<<<M_, 64>>>(sentence, embed, out_mask);

    gemm_pre<<<ggrid, 256>>>(emb, Wih_0f, Wih_0b, b_0f, b_0b, pre_f, pre_b, E_);
    lstm_layer<<<128, 256, LSTM_SMEM>>>(pre_f, pre_b, Whh_0f, Whh_0b, lengths, xcat,
                                        barp, hbase);

    gemm_pre<<<ggrid, 256>>>(xcat, Wih_1f, Wih_1b, b_1f, b_1b, pre_f, pre_b, 512);
    lstm_layer<<<128, 256, LSTM_SMEM>>>(pre_f, pre_b, Whh_1f, Whh_1b, lengths, xcat,
                                        barp + 2 * T_, hbase + 2 * 2 * H_ * B_);

    emit_kernel<<<M_ / 32, 256>>>(xcat, Wout, bout, emit, out_emit);
    crf_kernel<<<B_, 192>>>(emit, tags, lengths, start_t, end_t, trans, partp);
    finalize_kernel<<<1, 32>>>(out_loss);
    (void)in_sizes; (void)n_in; (void)out_size;
}